// round 10
// baseline (speedup 1.0000x reference)
#include <cuda_runtime.h>
#include <cuda_bf16.h>
#include <math.h>
#include <stdint.h>

#define DIMX 2048
#define KVDIM 512
#define QKV_N 3072
#define HD 64
#define NH 32
#define BATCH 2
#define SEQ 2048
#define M_ROWS (BATCH*SEQ)
#define QPAD 68     // float2 stride for Q/K interleaved hi/lo smem (flash)
#define VPAD 72     // float stride for V smem (flash)
#define ALDU 20     // uint32 row stride for bf16-pair smem tiles (GEMM)

// ---- scratch (module-static device memory) ----
__device__ __align__(16) __nv_bfloat16 g_w [QKV_N*DIMX];   // ternarized [wq;wk;wv], bf16
__device__ __align__(16) __nv_bfloat16 g_to[DIMX*DIMX];    // ternarized wo, bf16
__device__ float g_qh [(size_t)M_ROWS*QKV_N];
__device__ float g_ql [(size_t)M_ROWS*QKV_N];
__device__ float g_ao [(size_t)M_ROWS*DIMX];
__device__ float g_partial[4][1024];
__device__ float g_thresh[4];

__device__ __forceinline__ uint32_t f2tf(float f) {
    uint32_t u; asm("cvt.rna.tf32.f32 %0, %1;" : "=r"(u) : "f"(f)); return u;
}
__device__ __forceinline__ float f2tff(float f) { return __uint_as_float(f2tf(f)); }
__device__ __forceinline__ uint32_t fu(float f) { return __float_as_uint(f); }
__device__ __forceinline__ void split2(float v, float& hi, float& lo) {
    hi = f2tff(v);
    lo = f2tff(v - hi);
}
__device__ __forceinline__ float bfr(float v) {
    return __bfloat162float(__float2bfloat16(v));
}
__device__ __forceinline__ uint32_t packbf(float a, float b) {
    __nv_bfloat162 p = __floats2bfloat162_rn(a, b);
    return *reinterpret_cast<uint32_t*>(&p);
}

// ---- |w| mean (deterministic two-pass, float4) ----
__global__ void abs_partial_kernel(const float4* __restrict__ w, int n4, int slot) {
    __shared__ float sd[256];
    float s0 = 0.f, s1 = 0.f;
    int stride = gridDim.x * blockDim.x;
    for (int i = blockIdx.x*blockDim.x + threadIdx.x; i < n4; i += 2*stride) {
        float4 v = w[i];
        s0 += fabsf(v.x) + fabsf(v.y) + fabsf(v.z) + fabsf(v.w);
        int j = i + stride;
        if (j < n4) {
            float4 u = w[j];
            s1 += fabsf(u.x) + fabsf(u.y) + fabsf(u.z) + fabsf(u.w);
        }
    }
    sd[threadIdx.x] = s0 + s1;
    __syncthreads();
    for (int st = 128; st; st >>= 1) {
        if (threadIdx.x < st) sd[threadIdx.x] += sd[threadIdx.x + st];
        __syncthreads();
    }
    if (threadIdx.x == 0) g_partial[slot][blockIdx.x] = sd[0];
}

__global__ void finalize_kernel() {
    int slot = blockIdx.x;
    __shared__ float sd[256];
    float s = 0.f;
    for (int i = threadIdx.x; i < 1024; i += 256) s += g_partial[slot][i];
    sd[threadIdx.x] = s;
    __syncthreads();
    for (int st = 128; st; st >>= 1) {
        if (threadIdx.x < st) sd[threadIdx.x] += sd[threadIdx.x + st];
        __syncthreads();
    }
    if (threadIdx.x == 0) {
        const int ncounts[4] = {DIMX*DIMX, KVDIM*DIMX, KVDIM*DIMX, DIMX*DIMX};
        float scale = sd[0] / (float)ncounts[slot];
        g_thresh[slot] = 0.05f * fmaxf(scale, 1e-6f);
    }
}

// ternarize -> bf16 (exact for {-1,0,1})
__global__ void ternarize_kernel(const float4* __restrict__ w, uint2* __restrict__ t,
                                 int n4, int slot) {
    int i = blockIdx.x*256 + threadIdx.x;
    if (i >= n4) return;
    float th = g_thresh[slot];
    float4 v = w[i];
    float o0 = v.x > th ? 1.f : (v.x < -th ? -1.f : 0.f);
    float o1 = v.y > th ? 1.f : (v.y < -th ? -1.f : 0.f);
    float o2 = v.z > th ? 1.f : (v.z < -th ? -1.f : 0.f);
    float o3 = v.w > th ? 1.f : (v.w < -th ? -1.f : 0.f);
    t[i] = make_uint2(packbf(o0, o1), packbf(o2, o3));
}

#define MMA_BF16(d, a, b0v, b1v)                                             \
    asm volatile("mma.sync.aligned.m16n8k16.row.col.f32.bf16.bf16.f32 "      \
        "{%0,%1,%2,%3}, {%4,%5,%6,%7}, {%8,%9}, {%0,%1,%2,%3};"              \
        : "+f"(d[0]), "+f"(d[1]), "+f"(d[2]), "+f"(d[3])                     \
        : "r"(a[0]), "r"(a[1]), "r"(a[2]), "r"(a[3]), "r"(b0v), "r"(b1v))

#define MMA_TF32(d, a, b0v, b1v)                                             \
    asm volatile("mma.sync.aligned.m16n8k8.row.col.f32.tf32.tf32.f32 "       \
        "{%0,%1,%2,%3}, {%4,%5,%6,%7}, {%8,%9}, {%0,%1,%2,%3};"              \
        : "+f"(d[0]), "+f"(d[1]), "+f"(d[2]), "+f"(d[3])                     \
        : "r"(a[0]), "r"(a[1]), "r"(a[2]), "r"(a[3]), "r"(b0v), "r"(b1v))

// ---- C[M,N] = A[M,K] * B[N,K]^T, bf16 mma, A split into NSPLIT bf16 terms ----
// B is ternary bf16 (exact). Register-prefetch double buffer over 32-wide K chunks.
template<int NSPLIT, bool SPLIT_OUT>
__global__ __launch_bounds__(256) void mma_gemm_bf(
    const float* __restrict__ A, const __nv_bfloat16* __restrict__ B,
    float* __restrict__ C, float* __restrict__ Clo, int N, int K)
{
    extern __shared__ uint32_t smu[];
    uint32_t* As = smu;                       // NSPLIT * 128*ALDU
    uint32_t* Bs = smu + NSPLIT*128*ALDU;     // 128*ALDU
    int tid = threadIdx.x;
    int wid = tid >> 5, lane = tid & 31;
    int g = lane >> 2, t = lane & 3;
    int wm = (wid & 1) * 64, wn = (wid >> 1) * 32;

    float acc[4][4][4];
    #pragma unroll
    for (int mt = 0; mt < 4; mt++)
        #pragma unroll
        for (int nt = 0; nt < 4; nt++)
            #pragma unroll
            for (int r = 0; r < 4; r++) acc[mt][nt][r] = 0.f;

    int lr = tid >> 1;
    int half = tid & 1;
    int lc = half * 16;
    const float* Aptr = A + (size_t)(blockIdx.y*128 + lr)*K + lc;
    const __nv_bfloat16* Brow = B + (size_t)(blockIdx.x*128 + lr)*K + lc;

    float4 av[4];
    uint4 bv[2];

    auto sts_chunk = [&]() {
        const float* af = reinterpret_cast<const float*>(av);
        uint32_t ph[8], pm[8], pl[8];
        #pragma unroll
        for (int i = 0; i < 8; i++) {
            float v0 = af[2*i], v1 = af[2*i+1];
            float h0 = bfr(v0), h1 = bfr(v1);
            float r0 = v0 - h0, r1 = v1 - h1;
            ph[i] = packbf(h0, h1);
            if (NSPLIT == 2) {
                pm[i] = packbf(r0, r1);
            } else {
                float m0 = bfr(r0), m1 = bfr(r1);
                pm[i] = packbf(m0, m1);
                pl[i] = packbf(r0 - m0, r1 - m1);
            }
        }
        uint32_t* d0 = As + lr*ALDU + half*8;
        *reinterpret_cast<uint4*>(d0)     = make_uint4(ph[0],ph[1],ph[2],ph[3]);
        *reinterpret_cast<uint4*>(d0 + 4) = make_uint4(ph[4],ph[5],ph[6],ph[7]);
        uint32_t* d1 = d0 + 128*ALDU;
        *reinterpret_cast<uint4*>(d1)     = make_uint4(pm[0],pm[1],pm[2],pm[3]);
        *reinterpret_cast<uint4*>(d1 + 4) = make_uint4(pm[4],pm[5],pm[6],pm[7]);
        if (NSPLIT == 3) {
            uint32_t* d2 = d1 + 128*ALDU;
            *reinterpret_cast<uint4*>(d2)     = make_uint4(pl[0],pl[1],pl[2],pl[3]);
            *reinterpret_cast<uint4*>(d2 + 4) = make_uint4(pl[4],pl[5],pl[6],pl[7]);
        }
        uint32_t* db = Bs + lr*ALDU + half*8;
        *reinterpret_cast<uint4*>(db)     = bv[0];
        *reinterpret_cast<uint4*>(db + 4) = bv[1];
    };

    // prologue
    #pragma unroll
    for (int i = 0; i < 4; i++)
        av[i] = *reinterpret_cast<const float4*>(Aptr + 4*i);
    {
        const uint4* p = reinterpret_cast<const uint4*>(Brow);
        bv[0] = p[0]; bv[1] = p[1];
    }
    sts_chunk();
    __syncthreads();

    for (int k0 = 32; k0 <= K; k0 += 32) {
        bool more = (k0 < K);
        if (more) {
            #pragma unroll
            for (int i = 0; i < 4; i++)
                av[i] = *reinterpret_cast<const float4*>(Aptr + k0 + 4*i);
            const uint4* p = reinterpret_cast<const uint4*>(Brow + k0);
            bv[0] = p[0]; bv[1] = p[1];
        }
        // compute current tile: 2 k16-steps
        #pragma unroll
        for (int s = 0; s < 2; s++) {
            uint32_t a[NSPLIT][4][4], b[4][2];
            #pragma unroll
            for (int mt = 0; mt < 4; mt++) {
                int row = wm + mt*16 + g;
                #pragma unroll
                for (int sp = 0; sp < NSPLIT; sp++) {
                    const uint32_t* pa = As + sp*(128*ALDU) + row*ALDU + s*8 + t;
                    a[sp][mt][0] = pa[0];
                    a[sp][mt][1] = pa[8*ALDU];
                    a[sp][mt][2] = pa[4];
                    a[sp][mt][3] = pa[8*ALDU + 4];
                }
            }
            #pragma unroll
            for (int nt = 0; nt < 4; nt++) {
                const uint32_t* pb = Bs + (wn + nt*8 + g)*ALDU + s*8 + t;
                b[nt][0] = pb[0];
                b[nt][1] = pb[4];
            }
            #pragma unroll
            for (int mt = 0; mt < 4; mt++)
                #pragma unroll
                for (int nt = 0; nt < 4; nt++)
                    #pragma unroll
                    for (int sp = 0; sp < NSPLIT; sp++)
                        MMA_BF16(acc[mt][nt], a[sp][mt], b[nt][0], b[nt][1]);
        }
        if (more) {
            __syncthreads();
            sts_chunk();
            __syncthreads();
        }
    }

    #pragma unroll
    for (int mt = 0; mt < 4; mt++) {
        int r0 = blockIdx.y*128 + wm + mt*16 + g;
        #pragma unroll
        for (int nt = 0; nt < 4; nt++) {
            int c = blockIdx.x*128 + wn + nt*8 + t*2;
            if (SPLIT_OUT) {
                float h0,l0,h1,l1,h2,l2,h3,l3;
                split2(acc[mt][nt][0], h0, l0); split2(acc[mt][nt][1], h1, l1);
                split2(acc[mt][nt][2], h2, l2); split2(acc[mt][nt][3], h3, l3);
                *reinterpret_cast<float2*>(C   + (size_t)r0*N + c)     = make_float2(h0, h1);
                *reinterpret_cast<float2*>(Clo + (size_t)r0*N + c)     = make_float2(l0, l1);
                *reinterpret_cast<float2*>(C   + (size_t)(r0+8)*N + c) = make_float2(h2, h3);
                *reinterpret_cast<float2*>(Clo + (size_t)(r0+8)*N + c) = make_float2(l2, l3);
            } else {
                *reinterpret_cast<float2*>(C + (size_t)r0*N + c) =
                    make_float2(acc[mt][nt][0], acc[mt][nt][1]);
                *reinterpret_cast<float2*>(C + (size_t)(r0+8)*N + c) =
                    make_float2(acc[mt][nt][2], acc[mt][nt][3]);
            }
        }
    }
}

// ---- GQA-merged causal flash attention (R6 body: no register prefetch) ----
__global__ __launch_bounds__(256) void flash_kernel(
    const float* __restrict__ Qhi, const float* __restrict__ Qlo,
    float* __restrict__ O)
{
    extern __shared__ float smf[];
    float2* Qs = reinterpret_cast<float2*>(smf);               // 256 x QPAD float2
    float2* Ks = reinterpret_cast<float2*>(smf + 256*QPAD*2);  // 64 x QPAD float2
    float*  Vs = smf + 256*QPAD*2 + 64*QPAD*2;                 // 64 x VPAD floats

    int gcomb = blockIdx.x;
    int gkv = gcomb >> 1;
    int b   = gcomb & 1;
    int qb  = 31 - blockIdx.y;       // heavy blocks first

    int tid = threadIdx.x;
    int wid = tid >> 5, lane = tid & 31;
    int g = lane >> 2, t = lane & 3;
    int hh = wid >> 1;
    int h  = gkv*4 + hh;
    int wr = (wid & 1) * 32;

    // load Q: 4 heads x 64 rows x 64 cols, {hi,lo} interleaved
    {
        size_t rowbase = (size_t)(b*SEQ + qb*64);
        #pragma unroll
        for (int it = 0; it < 32; it++) {
            int pidx = tid + it*256;
            int qrow = pidx >> 5;
            int c2 = pidx & 31;
            int head = gkv*4 + (qrow >> 6);
            size_t goff = (rowbase + (qrow & 63))*QKV_N + head*HD + c2*2;
            float2 hv = *reinterpret_cast<const float2*>(Qhi + goff);
            float2 lv = *reinterpret_cast<const float2*>(Qlo + goff);
            *reinterpret_cast<float4*>(&Qs[qrow*QPAD + c2*2]) =
                make_float4(hv.x, lv.x, hv.y, lv.y);
        }
    }

    float m_i[4], l_i[4];
    float o_acc[2][8][4];
    #pragma unroll
    for (int i = 0; i < 4; i++) { m_i[i] = -INFINITY; l_i[i] = 0.f; }
    #pragma unroll
    for (int mt = 0; mt < 2; mt++)
        #pragma unroll
        for (int dt = 0; dt < 8; dt++)
            #pragma unroll
            for (int r = 0; r < 4; r++) o_acc[mt][dt][r] = 0.f;

    for (int kb = 0; kb <= qb; kb++) {
        __syncthreads();   // prior PV reads done (also covers Q load at kb=0)
        {
            size_t krowbase = (size_t)(b*SEQ + kb*64);
            #pragma unroll
            for (int it = 0; it < 8; it++) {
                int pidx = tid + it*256;
                int kr = pidx >> 5, c2 = pidx & 31;
                size_t goff = (krowbase + kr)*QKV_N + DIMX + gkv*HD + c2*2;
                float2 hv = *reinterpret_cast<const float2*>(Qhi + goff);
                float2 lv = *reinterpret_cast<const float2*>(Qlo + goff);
                *reinterpret_cast<float4*>(&Ks[kr*QPAD + c2*2]) =
                    make_float4(hv.x, lv.x, hv.y, lv.y);
            }
            #pragma unroll
            for (int it = 0; it < 4; it++) {
                int fidx = tid + it*256;
                int vr = fidx >> 4, d4 = fidx & 15;
                size_t goff = (krowbase + vr)*QKV_N + DIMX + KVDIM + gkv*HD + d4*4;
                *reinterpret_cast<float4*>(&Vs[vr*VPAD + d4*4]) =
                    *reinterpret_cast<const float4*>(Qhi + goff);
            }
        }
        __syncthreads();

        // S = Q K^T (3-term tf32 split)
        float s[2][8][4];
        #pragma unroll
        for (int mt = 0; mt < 2; mt++)
            #pragma unroll
            for (int nt = 0; nt < 8; nt++)
                #pragma unroll
                for (int r = 0; r < 4; r++) s[mt][nt][r] = 0.f;

        #pragma unroll
        for (int ks = 0; ks < 8; ks++) {
            int kk = ks*8;
            uint32_t ah[2][4], al[2][4];
            #pragma unroll
            for (int mt = 0; mt < 2; mt++) {
                int row = hh*64 + wr + mt*16 + g;
                float2 q00 = Qs[row*QPAD + kk + t];
                float2 q01 = Qs[row*QPAD + kk + t + 4];
                float2 q10 = Qs[(row+8)*QPAD + kk + t];
                float2 q11 = Qs[(row+8)*QPAD + kk + t + 4];
                ah[mt][0] = fu(q00.x); al[mt][0] = fu(q00.y);
                ah[mt][1] = fu(q10.x); al[mt][1] = fu(q10.y);
                ah[mt][2] = fu(q01.x); al[mt][2] = fu(q01.y);
                ah[mt][3] = fu(q11.x); al[mt][3] = fu(q11.y);
            }
            #pragma unroll
            for (int nt = 0; nt < 8; nt++) {
                float2 k0 = Ks[(nt*8+g)*QPAD + kk + t];
                float2 k1 = Ks[(nt*8+g)*QPAD + kk + t + 4];
                uint32_t bh0 = fu(k0.x), bl0 = fu(k0.y);
                uint32_t bh1 = fu(k1.x), bl1 = fu(k1.y);
                #pragma unroll
                for (int mt = 0; mt < 2; mt++) {
                    MMA_TF32(s[mt][nt], ah[mt], bh0, bh1);
                    MMA_TF32(s[mt][nt], ah[mt], bl0, bl1);
                    MMA_TF32(s[mt][nt], al[mt], bh0, bh1);
                }
            }
        }

        const float smul = 0.125f;
        if (kb == qb) {
            #pragma unroll
            for (int mt = 0; mt < 2; mt++) {
                int qr = wr + mt*16 + g;
                #pragma unroll
                for (int nt = 0; nt < 8; nt++) {
                    int c0 = nt*8 + t*2;
                    s[mt][nt][0] = (c0     <= qr)     ? s[mt][nt][0]*smul : -INFINITY;
                    s[mt][nt][1] = (c0 + 1 <= qr)     ? s[mt][nt][1]*smul : -INFINITY;
                    s[mt][nt][2] = (c0     <= qr + 8) ? s[mt][nt][2]*smul : -INFINITY;
                    s[mt][nt][3] = (c0 + 1 <= qr + 8) ? s[mt][nt][3]*smul : -INFINITY;
                }
            }
        } else {
            #pragma unroll
            for (int mt = 0; mt < 2; mt++)
                #pragma unroll
                for (int nt = 0; nt < 8; nt++)
                    #pragma unroll
                    for (int r = 0; r < 4; r++) s[mt][nt][r] *= smul;
        }

        // online softmax
        #pragma unroll
        for (int mt = 0; mt < 2; mt++)
            #pragma unroll
            for (int rr = 0; rr < 2; rr++) {
                int si = mt*2 + rr;
                float mx = -INFINITY;
                #pragma unroll
                for (int nt = 0; nt < 8; nt++)
                    mx = fmaxf(mx, fmaxf(s[mt][nt][2*rr], s[mt][nt][2*rr+1]));
                mx = fmaxf(mx, __shfl_xor_sync(0xffffffffu, mx, 1));
                mx = fmaxf(mx, __shfl_xor_sync(0xffffffffu, mx, 2));
                float m_new = fmaxf(m_i[si], mx);
                float alpha = __expf(m_i[si] - m_new);
                float rs = 0.f;
                #pragma unroll
                for (int nt = 0; nt < 8; nt++) {
                    float p0 = __expf(s[mt][nt][2*rr]   - m_new);
                    float p1 = __expf(s[mt][nt][2*rr+1] - m_new);
                    s[mt][nt][2*rr] = p0; s[mt][nt][2*rr+1] = p1;
                    rs += p0 + p1;
                }
                rs += __shfl_xor_sync(0xffffffffu, rs, 1);
                rs += __shfl_xor_sync(0xffffffffu, rs, 2);
                l_i[si] = l_i[si]*alpha + rs;
                m_i[si] = m_new;
                #pragma unroll
                for (int dt = 0; dt < 8; dt++) {
                    o_acc[mt][dt][2*rr]   *= alpha;
                    o_acc[mt][dt][2*rr+1] *= alpha;
                }
            }

        // O += P V (single tf32; P a-frag via shuffles)
        #pragma unroll
        for (int ks = 0; ks < 8; ks++) {
            int kk = ks*8;
            uint32_t pa[2][4];
            int srcA = (lane & 28) | (t >> 1);
            int srcB = srcA + 2;
            #pragma unroll
            for (int mt = 0; mt < 2; mt++) {
                float x0 = __shfl_sync(0xffffffffu, s[mt][ks][0], srcA);
                float x1 = __shfl_sync(0xffffffffu, s[mt][ks][1], srcA);
                float y0 = __shfl_sync(0xffffffffu, s[mt][ks][0], srcB);
                float y1 = __shfl_sync(0xffffffffu, s[mt][ks][1], srcB);
                float x2 = __shfl_sync(0xffffffffu, s[mt][ks][2], srcA);
                float x3 = __shfl_sync(0xffffffffu, s[mt][ks][3], srcA);
                float y2 = __shfl_sync(0xffffffffu, s[mt][ks][2], srcB);
                float y3 = __shfl_sync(0xffffffffu, s[mt][ks][3], srcB);
                float a0 = (t & 1) ? x1 : x0;
                float a1 = (t & 1) ? x3 : x2;
                float a2 = (t & 1) ? y1 : y0;
                float a3 = (t & 1) ? y3 : y2;
                pa[mt][0] = f2tf(a0); pa[mt][1] = f2tf(a1);
                pa[mt][2] = f2tf(a2); pa[mt][3] = f2tf(a3);
            }
            #pragma unroll
            for (int dt = 0; dt < 8; dt++) {
                uint32_t v0 = fu(Vs[(kk+t)*VPAD + dt*8 + g]);
                uint32_t v1 = fu(Vs[(kk+t+4)*VPAD + dt*8 + g]);
                MMA_TF32(o_acc[0][dt], pa[0], v0, v1);
                MMA_TF32(o_acc[1][dt], pa[1], v0, v1);
            }
        }
    }

    #pragma unroll
    for (int mt = 0; mt < 2; mt++) {
        float inv0 = 1.f / l_i[mt*2];
        float inv1 = 1.f / l_i[mt*2+1];
        float* Og = O + (size_t)(b*SEQ + qb*64 + wr + mt*16 + g)*DIMX + h*HD;
        #pragma unroll
        for (int dt = 0; dt < 8; dt++) {
            *reinterpret_cast<float2*>(Og + dt*8 + t*2) =
                make_float2(o_acc[mt][dt][0]*inv0, o_acc[mt][dt][1]*inv0);
            *reinterpret_cast<float2*>(Og + (size_t)8*DIMX + dt*8 + t*2) =
                make_float2(o_acc[mt][dt][2]*inv1, o_acc[mt][dt][3]*inv1);
        }
    }
}

extern "C" void kernel_launch(void* const* d_in, const int* in_sizes, int n_in,
                              void* d_out, int out_size)
{
    const float* x  = (const float*)d_in[0];
    const float* wq = (const float*)d_in[1];
    const float* wk = (const float*)d_in[2];
    const float* wv = (const float*)d_in[3];
    const float* wo = (const float*)d_in[4];
    float* out = (float*)d_out;

    __nv_bfloat16 *w3, *to;
    float *qh, *ql, *ao;
    cudaGetSymbolAddress((void**)&w3, g_w);
    cudaGetSymbolAddress((void**)&to, g_to);
    cudaGetSymbolAddress((void**)&qh, g_qh);
    cudaGetSymbolAddress((void**)&ql, g_ql);
    cudaGetSymbolAddress((void**)&ao, g_ao);

    abs_partial_kernel<<<1024, 256>>>((const float4*)wq, DIMX*DIMX/4,  0);
    abs_partial_kernel<<<1024, 256>>>((const float4*)wk, KVDIM*DIMX/4, 1);
    abs_partial_kernel<<<1024, 256>>>((const float4*)wv, KVDIM*DIMX/4, 2);
    abs_partial_kernel<<<1024, 256>>>((const float4*)wo, DIMX*DIMX/4,  3);
    finalize_kernel<<<4, 256>>>();

    ternarize_kernel<<<(DIMX*DIMX/4)/256,  256>>>((const float4*)wq, (uint2*)w3, DIMX*DIMX/4, 0);
    ternarize_kernel<<<(KVDIM*DIMX/4)/256, 256>>>((const float4*)wk,
        (uint2*)(w3 + (size_t)DIMX*DIMX), KVDIM*DIMX/4, 1);
    ternarize_kernel<<<(KVDIM*DIMX/4)/256, 256>>>((const float4*)wv,
        (uint2*)(w3 + (size_t)DIMX*DIMX + (size_t)KVDIM*DIMX), KVDIM*DIMX/4, 2);
    ternarize_kernel<<<(DIMX*DIMX/4)/256,  256>>>((const float4*)wo, (uint2*)to, DIMX*DIMX/4, 3);

    // QKV projection: bf16 3-split A (captures full fp32 precision), split outputs
    int gsm1 = (3*128*ALDU + 128*ALDU) * 4;
    cudaFuncSetAttribute(mma_gemm_bf<3,true>,
                         cudaFuncAttributeMaxDynamicSharedMemorySize, gsm1);
    mma_gemm_bf<3,true><<<dim3(QKV_N/128, M_ROWS/128), 256, gsm1>>>(
        x, w3, qh, ql, QKV_N, DIMX);

    // attention (GQA-merged, R6 body)
    int fsm = (256*QPAD*2 + 64*QPAD*2 + 64*VPAD) * 4;
    cudaFuncSetAttribute(flash_kernel,
                         cudaFuncAttributeMaxDynamicSharedMemorySize, fsm);
    flash_kernel<<<dim3(16, 32), 256, fsm>>>(qh, ql, ao);

    // output projection: bf16 2-split A (residual 1.5e-5, better than tf32-single)
    int gsm2 = (2*128*ALDU + 128*ALDU) * 4;
    cudaFuncSetAttribute(mma_gemm_bf<2,false>,
                         cudaFuncAttributeMaxDynamicSharedMemorySize, gsm2);
    mma_gemm_bf<2,false><<<dim3(DIMX/128, M_ROWS/128), 256, gsm2>>>(
        ao, to, out, nullptr, DIMX, DIMX);
}

// round 11
// speedup vs baseline: 1.0558x; 1.0558x over previous
#include <cuda_runtime.h>
#include <cuda_bf16.h>
#include <math.h>
#include <stdint.h>

#define DIMX 2048
#define KVDIM 512
#define QKV_N 3072
#define HD 64
#define NH 32
#define BATCH 2
#define SEQ 2048
#define M_ROWS (BATCH*SEQ)
#define QPAD 68     // float2 stride for Q/K interleaved hi/lo smem (flash)
#define VPAD 72     // float stride for V smem (flash)
#define ALDU 20     // uint32 row stride for bf16-pair smem tiles (GEMM)

// ---- scratch (module-static device memory) ----
__device__ __align__(16) __nv_bfloat16 g_w  [QKV_N*DIMX];       // ternarized [wq;wk;wv]
__device__ __align__(16) __nv_bfloat16 g_to [DIMX*DIMX];        // ternarized wo
__device__ __align__(16) __nv_bfloat16 g_xs [(size_t)3*M_ROWS*DIMX];  // x 3-split planes
__device__ __align__(16) __nv_bfloat16 g_aos[(size_t)2*M_ROWS*DIMX];  // ao 2-split planes
__device__ float g_qh [(size_t)M_ROWS*QKV_N];
__device__ float g_ql [(size_t)M_ROWS*QKV_N];
__device__ float g_ao [(size_t)M_ROWS*DIMX];
__device__ float g_partial[4][256];
__device__ float g_thresh[4];

__device__ __forceinline__ uint32_t f2tf(float f) {
    uint32_t u; asm("cvt.rna.tf32.f32 %0, %1;" : "=r"(u) : "f"(f)); return u;
}
__device__ __forceinline__ float f2tff(float f) { return __uint_as_float(f2tf(f)); }
__device__ __forceinline__ uint32_t fu(float f) { return __float_as_uint(f); }
__device__ __forceinline__ void split2(float v, float& hi, float& lo) {
    hi = f2tff(v);
    lo = f2tff(v - hi);
}
__device__ __forceinline__ float bfr(float v) {
    return __bfloat162float(__float2bfloat16(v));
}
__device__ __forceinline__ uint32_t packbf(float a, float b) {
    __nv_bfloat162 p = __floats2bfloat162_rn(a, b);
    return *reinterpret_cast<uint32_t*>(&p);
}
__device__ __forceinline__ uint32_t smem_u32(const void* p) {
    uint32_t a;
    asm("{ .reg .u64 t; cvta.to.shared.u64 t, %1; cvt.u32.u64 %0, t; }" : "=r"(a) : "l"(p));
    return a;
}
#define CP16(dst, src) \
    asm volatile("cp.async.cg.shared.global [%0], [%1], 16;" :: "r"(dst), "l"(src))
#define CP_COMMIT()  asm volatile("cp.async.commit_group;" ::: "memory")
#define CP_WAIT1()   asm volatile("cp.async.wait_group 1;" ::: "memory")

// ---- fused |w| mean, pass 1 (grid.y = slot) ----
__global__ void abs_all_kernel(const float4* __restrict__ wq, const float4* __restrict__ wk,
                               const float4* __restrict__ wv, const float4* __restrict__ wo) {
    __shared__ float sd[256];
    int slot = blockIdx.y;
    const float4* w = slot == 0 ? wq : slot == 1 ? wk : slot == 2 ? wv : wo;
    int n4 = (slot == 0 || slot == 3) ? DIMX*DIMX/4 : KVDIM*DIMX/4;
    float s = 0.f;
    int stride = gridDim.x * blockDim.x;
    for (int i = blockIdx.x*blockDim.x + threadIdx.x; i < n4; i += stride) {
        float4 v = w[i];
        s += fabsf(v.x) + fabsf(v.y) + fabsf(v.z) + fabsf(v.w);
    }
    sd[threadIdx.x] = s;
    __syncthreads();
    for (int st = 128; st; st >>= 1) {
        if (threadIdx.x < st) sd[threadIdx.x] += sd[threadIdx.x + st];
        __syncthreads();
    }
    if (threadIdx.x == 0) g_partial[slot][blockIdx.x] = sd[0];
}

__global__ void finalize_kernel() {
    int slot = blockIdx.x;
    __shared__ float sd[256];
    sd[threadIdx.x] = g_partial[slot][threadIdx.x];
    __syncthreads();
    for (int st = 128; st; st >>= 1) {
        if (threadIdx.x < st) sd[threadIdx.x] += sd[threadIdx.x + st];
        __syncthreads();
    }
    if (threadIdx.x == 0) {
        const int ncounts[4] = {DIMX*DIMX, KVDIM*DIMX, KVDIM*DIMX, DIMX*DIMX};
        float scale = sd[0] / (float)ncounts[slot];
        g_thresh[slot] = 0.05f * fmaxf(scale, 1e-6f);
    }
}

// ---- fused ternarize -> bf16 (grid.y = slot) ----
__global__ void tern_all_kernel(const float4* __restrict__ wq, const float4* __restrict__ wk,
                                const float4* __restrict__ wv, const float4* __restrict__ wo,
                                uint2* __restrict__ w3, uint2* __restrict__ to) {
    int slot = blockIdx.y;
    int n4 = (slot == 0 || slot == 3) ? DIMX*DIMX/4 : KVDIM*DIMX/4;
    int i = blockIdx.x*256 + threadIdx.x;
    if (i >= n4) return;
    const float4* w = slot == 0 ? wq : slot == 1 ? wk : slot == 2 ? wv : wo;
    uint2* dst = slot == 0 ? w3
               : slot == 1 ? (w3 + DIMX*DIMX/4)
               : slot == 2 ? (w3 + DIMX*DIMX/4 + KVDIM*DIMX/4)
               : to;
    float th = g_thresh[slot];
    float4 v = w[i];
    float o0 = v.x > th ? 1.f : (v.x < -th ? -1.f : 0.f);
    float o1 = v.y > th ? 1.f : (v.y < -th ? -1.f : 0.f);
    float o2 = v.z > th ? 1.f : (v.z < -th ? -1.f : 0.f);
    float o3 = v.w > th ? 1.f : (v.w < -th ? -1.f : 0.f);
    dst[i] = make_uint2(packbf(o0, o1), packbf(o2, o3));
}

// ---- split fp32 -> NS bf16 planes (plane stride = n4 uint2 entries) ----
template<int NS>
__global__ void split_bf_kernel(const float4* __restrict__ src, uint2* __restrict__ dst, int n4) {
    int i = blockIdx.x*256 + threadIdx.x;
    if (i >= n4) return;
    float4 v = src[i];
    float h0 = bfr(v.x), h1 = bfr(v.y), h2 = bfr(v.z), h3 = bfr(v.w);
    dst[i] = make_uint2(packbf(h0, h1), packbf(h2, h3));
    float r0 = v.x - h0, r1 = v.y - h1, r2 = v.z - h2, r3 = v.w - h3;
    if (NS == 2) {
        dst[i + (size_t)n4] = make_uint2(packbf(r0, r1), packbf(r2, r3));
    } else {
        float m0 = bfr(r0), m1 = bfr(r1), m2 = bfr(r2), m3 = bfr(r3);
        dst[i + (size_t)n4] = make_uint2(packbf(m0, m1), packbf(m2, m3));
        dst[i + (size_t)2*n4] =
            make_uint2(packbf(r0 - m0, r1 - m1), packbf(r2 - m2, r3 - m3));
    }
}

#define MMA_BF16(d, a, b0v, b1v)                                             \
    asm volatile("mma.sync.aligned.m16n8k16.row.col.f32.bf16.bf16.f32 "      \
        "{%0,%1,%2,%3}, {%4,%5,%6,%7}, {%8,%9}, {%0,%1,%2,%3};"              \
        : "+f"(d[0]), "+f"(d[1]), "+f"(d[2]), "+f"(d[3])                     \
        : "r"(a[0]), "r"(a[1]), "r"(a[2]), "r"(a[3]), "r"(b0v), "r"(b1v))

#define MMA_TF32(d, a, b0v, b1v)                                             \
    asm volatile("mma.sync.aligned.m16n8k8.row.col.f32.tf32.tf32.f32 "       \
        "{%0,%1,%2,%3}, {%4,%5,%6,%7}, {%8,%9}, {%0,%1,%2,%3};"              \
        : "+f"(d[0]), "+f"(d[1]), "+f"(d[2]), "+f"(d[3])                     \
        : "r"(a[0]), "r"(a[1]), "r"(a[2]), "r"(a[3]), "r"(b0v), "r"(b1v))

// ---- C[M,N] = A*B^T, all-bf16 cp.async double-buffered pipeline ----
// A: NSPLIT pre-split bf16 planes [NSPLIT][Mtot][K]; B: ternary bf16 [N][K].
template<int NSPLIT, bool SPLIT_OUT>
__global__ __launch_bounds__(256) void gemm_async(
    const __nv_bfloat16* __restrict__ Abf, const __nv_bfloat16* __restrict__ B,
    float* __restrict__ C, float* __restrict__ Clo, int Mtot, int N, int K)
{
    extern __shared__ __align__(16) uint32_t smu[];
    const int STG_U32 = (NSPLIT+1)*128*ALDU;
    int tid = threadIdx.x;
    int wid = tid >> 5, lane = tid & 31;
    int g = lane >> 2, t = lane & 3;
    int wm = (wid & 1) * 64, wn = (wid >> 1) * 32;
    int lr = tid >> 1, half = tid & 1;

    uint32_t sb = smem_u32(smu);
    uint32_t stBase[2] = { sb, sb + (uint32_t)STG_U32*4 };

    int brow = blockIdx.y*128 + lr;
    const __nv_bfloat16* Brow = B + (size_t)(blockIdx.x*128 + lr)*K;

    float acc[4][4][4];
    #pragma unroll
    for (int mt = 0; mt < 4; mt++)
        #pragma unroll
        for (int nt = 0; nt < 4; nt++)
            #pragma unroll
            for (int r = 0; r < 4; r++) acc[mt][nt][r] = 0.f;

    auto issue = [&](int c, int stg) {
        int k0 = c*32;
        #pragma unroll
        for (int sp = 0; sp < NSPLIT; sp++) {
            const __nv_bfloat16* src = Abf + ((size_t)sp*Mtot + brow)*K + k0 + half*16;
            uint32_t dst = stBase[stg] + (uint32_t)((sp*128 + lr)*ALDU + half*8)*4;
            CP16(dst, src);
            CP16(dst + 16, src + 8);
        }
        const __nv_bfloat16* bs = Brow + k0 + half*16;
        uint32_t dstb = stBase[stg] + (uint32_t)((NSPLIT*128 + lr)*ALDU + half*8)*4;
        CP16(dstb, bs);
        CP16(dstb + 16, bs + 8);
        CP_COMMIT();
    };

    int nch = K/32;
    issue(0, 0);
    issue(1, 1);

    for (int c = 0; c < nch; c++) {
        CP_WAIT1();
        __syncthreads();
        int stg = c & 1;
        const uint32_t* As = smu + stg*STG_U32;
        const uint32_t* Bs = As + NSPLIT*128*ALDU;
        #pragma unroll
        for (int s = 0; s < 2; s++) {
            uint32_t a[NSPLIT][4][4], b[4][2];
            #pragma unroll
            for (int mt = 0; mt < 4; mt++) {
                int row = wm + mt*16 + g;
                #pragma unroll
                for (int sp = 0; sp < NSPLIT; sp++) {
                    const uint32_t* pa = As + sp*(128*ALDU) + row*ALDU + s*8 + t;
                    a[sp][mt][0] = pa[0];
                    a[sp][mt][1] = pa[8*ALDU];
                    a[sp][mt][2] = pa[4];
                    a[sp][mt][3] = pa[8*ALDU + 4];
                }
            }
            #pragma unroll
            for (int nt = 0; nt < 4; nt++) {
                const uint32_t* pb = Bs + (wn + nt*8 + g)*ALDU + s*8 + t;
                b[nt][0] = pb[0];
                b[nt][1] = pb[4];
            }
            #pragma unroll
            for (int mt = 0; mt < 4; mt++)
                #pragma unroll
                for (int nt = 0; nt < 4; nt++)
                    #pragma unroll
                    for (int sp = 0; sp < NSPLIT; sp++)
                        MMA_BF16(acc[mt][nt], a[sp][mt], b[nt][0], b[nt][1]);
        }
        __syncthreads();
        if (c + 2 < nch) issue(c + 2, stg);
        else CP_COMMIT();   // keep group count aligned for CP_WAIT1
    }

    #pragma unroll
    for (int mt = 0; mt < 4; mt++) {
        int r0 = blockIdx.y*128 + wm + mt*16 + g;
        #pragma unroll
        for (int nt = 0; nt < 4; nt++) {
            int c = blockIdx.x*128 + wn + nt*8 + t*2;
            if (SPLIT_OUT) {
                float h0,l0,h1,l1,h2,l2,h3,l3;
                split2(acc[mt][nt][0], h0, l0); split2(acc[mt][nt][1], h1, l1);
                split2(acc[mt][nt][2], h2, l2); split2(acc[mt][nt][3], h3, l3);
                *reinterpret_cast<float2*>(C   + (size_t)r0*N + c)     = make_float2(h0, h1);
                *reinterpret_cast<float2*>(Clo + (size_t)r0*N + c)     = make_float2(l0, l1);
                *reinterpret_cast<float2*>(C   + (size_t)(r0+8)*N + c) = make_float2(h2, h3);
                *reinterpret_cast<float2*>(Clo + (size_t)(r0+8)*N + c) = make_float2(l2, l3);
            } else {
                *reinterpret_cast<float2*>(C + (size_t)r0*N + c) =
                    make_float2(acc[mt][nt][0], acc[mt][nt][1]);
                *reinterpret_cast<float2*>(C + (size_t)(r0+8)*N + c) =
                    make_float2(acc[mt][nt][2], acc[mt][nt][3]);
            }
        }
    }
}

// ---- GQA-merged causal flash attention (R10 body, unchanged) ----
__global__ __launch_bounds__(256) void flash_kernel(
    const float* __restrict__ Qhi, const float* __restrict__ Qlo,
    float* __restrict__ O)
{
    extern __shared__ float smf[];
    float2* Qs = reinterpret_cast<float2*>(smf);
    float2* Ks = reinterpret_cast<float2*>(smf + 256*QPAD*2);
    float*  Vs = smf + 256*QPAD*2 + 64*QPAD*2;

    int gcomb = blockIdx.x;
    int gkv = gcomb >> 1;
    int b   = gcomb & 1;
    int qb  = 31 - blockIdx.y;

    int tid = threadIdx.x;
    int wid = tid >> 5, lane = tid & 31;
    int g = lane >> 2, t = lane & 3;
    int hh = wid >> 1;
    int h  = gkv*4 + hh;
    int wr = (wid & 1) * 32;

    {
        size_t rowbase = (size_t)(b*SEQ + qb*64);
        #pragma unroll
        for (int it = 0; it < 32; it++) {
            int pidx = tid + it*256;
            int qrow = pidx >> 5;
            int c2 = pidx & 31;
            int head = gkv*4 + (qrow >> 6);
            size_t goff = (rowbase + (qrow & 63))*QKV_N + head*HD + c2*2;
            float2 hv = *reinterpret_cast<const float2*>(Qhi + goff);
            float2 lv = *reinterpret_cast<const float2*>(Qlo + goff);
            *reinterpret_cast<float4*>(&Qs[qrow*QPAD + c2*2]) =
                make_float4(hv.x, lv.x, hv.y, lv.y);
        }
    }

    float m_i[4], l_i[4];
    float o_acc[2][8][4];
    #pragma unroll
    for (int i = 0; i < 4; i++) { m_i[i] = -INFINITY; l_i[i] = 0.f; }
    #pragma unroll
    for (int mt = 0; mt < 2; mt++)
        #pragma unroll
        for (int dt = 0; dt < 8; dt++)
            #pragma unroll
            for (int r = 0; r < 4; r++) o_acc[mt][dt][r] = 0.f;

    for (int kb = 0; kb <= qb; kb++) {
        __syncthreads();
        {
            size_t krowbase = (size_t)(b*SEQ + kb*64);
            #pragma unroll
            for (int it = 0; it < 8; it++) {
                int pidx = tid + it*256;
                int kr = pidx >> 5, c2 = pidx & 31;
                size_t goff = (krowbase + kr)*QKV_N + DIMX + gkv*HD + c2*2;
                float2 hv = *reinterpret_cast<const float2*>(Qhi + goff);
                float2 lv = *reinterpret_cast<const float2*>(Qlo + goff);
                *reinterpret_cast<float4*>(&Ks[kr*QPAD + c2*2]) =
                    make_float4(hv.x, lv.x, hv.y, lv.y);
            }
            #pragma unroll
            for (int it = 0; it < 4; it++) {
                int fidx = tid + it*256;
                int vr = fidx >> 4, d4 = fidx & 15;
                size_t goff = (krowbase + vr)*QKV_N + DIMX + KVDIM + gkv*HD + d4*4;
                *reinterpret_cast<float4*>(&Vs[vr*VPAD + d4*4]) =
                    *reinterpret_cast<const float4*>(Qhi + goff);
            }
        }
        __syncthreads();

        float s[2][8][4];
        #pragma unroll
        for (int mt = 0; mt < 2; mt++)
            #pragma unroll
            for (int nt = 0; nt < 8; nt++)
                #pragma unroll
                for (int r = 0; r < 4; r++) s[mt][nt][r] = 0.f;

        #pragma unroll
        for (int ks = 0; ks < 8; ks++) {
            int kk = ks*8;
            uint32_t ah[2][4], al[2][4];
            #pragma unroll
            for (int mt = 0; mt < 2; mt++) {
                int row = hh*64 + wr + mt*16 + g;
                float2 q00 = Qs[row*QPAD + kk + t];
                float2 q01 = Qs[row*QPAD + kk + t + 4];
                float2 q10 = Qs[(row+8)*QPAD + kk + t];
                float2 q11 = Qs[(row+8)*QPAD + kk + t + 4];
                ah[mt][0] = fu(q00.x); al[mt][0] = fu(q00.y);
                ah[mt][1] = fu(q10.x); al[mt][1] = fu(q10.y);
                ah[mt][2] = fu(q01.x); al[mt][2] = fu(q01.y);
                ah[mt][3] = fu(q11.x); al[mt][3] = fu(q11.y);
            }
            #pragma unroll
            for (int nt = 0; nt < 8; nt++) {
                float2 k0 = Ks[(nt*8+g)*QPAD + kk + t];
                float2 k1 = Ks[(nt*8+g)*QPAD + kk + t + 4];
                uint32_t bh0 = fu(k0.x), bl0 = fu(k0.y);
                uint32_t bh1 = fu(k1.x), bl1 = fu(k1.y);
                #pragma unroll
                for (int mt = 0; mt < 2; mt++) {
                    MMA_TF32(s[mt][nt], ah[mt], bh0, bh1);
                    MMA_TF32(s[mt][nt], ah[mt], bl0, bl1);
                    MMA_TF32(s[mt][nt], al[mt], bh0, bh1);
                }
            }
        }

        const float smul = 0.125f;
        if (kb == qb) {
            #pragma unroll
            for (int mt = 0; mt < 2; mt++) {
                int qr = wr + mt*16 + g;
                #pragma unroll
                for (int nt = 0; nt < 8; nt++) {
                    int c0 = nt*8 + t*2;
                    s[mt][nt][0] = (c0     <= qr)     ? s[mt][nt][0]*smul : -INFINITY;
                    s[mt][nt][1] = (c0 + 1 <= qr)     ? s[mt][nt][1]*smul : -INFINITY;
                    s[mt][nt][2] = (c0     <= qr + 8) ? s[mt][nt][2]*smul : -INFINITY;
                    s[mt][nt][3] = (c0 + 1 <= qr + 8) ? s[mt][nt][3]*smul : -INFINITY;
                }
            }
        } else {
            #pragma unroll
            for (int mt = 0; mt < 2; mt++)
                #pragma unroll
                for (int nt = 0; nt < 8; nt++)
                    #pragma unroll
                    for (int r = 0; r < 4; r++) s[mt][nt][r] *= smul;
        }

        #pragma unroll
        for (int mt = 0; mt < 2; mt++)
            #pragma unroll
            for (int rr = 0; rr < 2; rr++) {
                int si = mt*2 + rr;
                float mx = -INFINITY;
                #pragma unroll
                for (int nt = 0; nt < 8; nt++)
                    mx = fmaxf(mx, fmaxf(s[mt][nt][2*rr], s[mt][nt][2*rr+1]));
                mx = fmaxf(mx, __shfl_xor_sync(0xffffffffu, mx, 1));
                mx = fmaxf(mx, __shfl_xor_sync(0xffffffffu, mx, 2));
                float m_new = fmaxf(m_i[si], mx);
                float alpha = __expf(m_i[si] - m_new);
                float rs = 0.f;
                #pragma unroll
                for (int nt = 0; nt < 8; nt++) {
                    float p0 = __expf(s[mt][nt][2*rr]   - m_new);
                    float p1 = __expf(s[mt][nt][2*rr+1] - m_new);
                    s[mt][nt][2*rr] = p0; s[mt][nt][2*rr+1] = p1;
                    rs += p0 + p1;
                }
                rs += __shfl_xor_sync(0xffffffffu, rs, 1);
                rs += __shfl_xor_sync(0xffffffffu, rs, 2);
                l_i[si] = l_i[si]*alpha + rs;
                m_i[si] = m_new;
                #pragma unroll
                for (int dt = 0; dt < 8; dt++) {
                    o_acc[mt][dt][2*rr]   *= alpha;
                    o_acc[mt][dt][2*rr+1] *= alpha;
                }
            }

        #pragma unroll
        for (int ks = 0; ks < 8; ks++) {
            int kk = ks*8;
            uint32_t pa[2][4];
            int srcA = (lane & 28) | (t >> 1);
            int srcB = srcA + 2;
            #pragma unroll
            for (int mt = 0; mt < 2; mt++) {
                float x0 = __shfl_sync(0xffffffffu, s[mt][ks][0], srcA);
                float x1 = __shfl_sync(0xffffffffu, s[mt][ks][1], srcA);
                float y0 = __shfl_sync(0xffffffffu, s[mt][ks][0], srcB);
                float y1 = __shfl_sync(0xffffffffu, s[mt][ks][1], srcB);
                float x2 = __shfl_sync(0xffffffffu, s[mt][ks][2], srcA);
                float x3 = __shfl_sync(0xffffffffu, s[mt][ks][3], srcA);
                float y2 = __shfl_sync(0xffffffffu, s[mt][ks][2], srcB);
                float y3 = __shfl_sync(0xffffffffu, s[mt][ks][3], srcB);
                float a0 = (t & 1) ? x1 : x0;
                float a1 = (t & 1) ? x3 : x2;
                float a2 = (t & 1) ? y1 : y0;
                float a3 = (t & 1) ? y3 : y2;
                pa[mt][0] = f2tf(a0); pa[mt][1] = f2tf(a1);
                pa[mt][2] = f2tf(a2); pa[mt][3] = f2tf(a3);
            }
            #pragma unroll
            for (int dt = 0; dt < 8; dt++) {
                uint32_t v0 = fu(Vs[(kk+t)*VPAD + dt*8 + g]);
                uint32_t v1 = fu(Vs[(kk+t+4)*VPAD + dt*8 + g]);
                MMA_TF32(o_acc[0][dt], pa[0], v0, v1);
                MMA_TF32(o_acc[1][dt], pa[1], v0, v1);
            }
        }
    }

    #pragma unroll
    for (int mt = 0; mt < 2; mt++) {
        float inv0 = 1.f / l_i[mt*2];
        float inv1 = 1.f / l_i[mt*2+1];
        float* Og = O + (size_t)(b*SEQ + qb*64 + wr + mt*16 + g)*DIMX + h*HD;
        #pragma unroll
        for (int dt = 0; dt < 8; dt++) {
            *reinterpret_cast<float2*>(Og + dt*8 + t*2) =
                make_float2(o_acc[mt][dt][0]*inv0, o_acc[mt][dt][1]*inv0);
            *reinterpret_cast<float2*>(Og + (size_t)8*DIMX + dt*8 + t*2) =
                make_float2(o_acc[mt][dt][2]*inv1, o_acc[mt][dt][3]*inv1);
        }
    }
}

extern "C" void kernel_launch(void* const* d_in, const int* in_sizes, int n_in,
                              void* d_out, int out_size)
{
    const float* x  = (const float*)d_in[0];
    const float* wq = (const float*)d_in[1];
    const float* wk = (const float*)d_in[2];
    const float* wv = (const float*)d_in[3];
    const float* wo = (const float*)d_in[4];
    float* out = (float*)d_out;

    __nv_bfloat16 *w3, *to, *xs, *aos;
    float *qh, *ql, *ao;
    cudaGetSymbolAddress((void**)&w3,  g_w);
    cudaGetSymbolAddress((void**)&to,  g_to);
    cudaGetSymbolAddress((void**)&xs,  g_xs);
    cudaGetSymbolAddress((void**)&aos, g_aos);
    cudaGetSymbolAddress((void**)&qh,  g_qh);
    cudaGetSymbolAddress((void**)&ql,  g_ql);
    cudaGetSymbolAddress((void**)&ao,  g_ao);

    // 1) fused |w| mean + thresholds
    abs_all_kernel<<<dim3(256, 4), 256>>>((const float4*)wq, (const float4*)wk,
                                          (const float4*)wv, (const float4*)wo);
    finalize_kernel<<<4, 256>>>();

    // 2) fused ternarize -> bf16
    tern_all_kernel<<<dim3(DIMX*DIMX/4/256, 4), 256>>>(
        (const float4*)wq, (const float4*)wk, (const float4*)wv, (const float4*)wo,
        (uint2*)w3, (uint2*)to);

    // 3) pre-split x into 3 bf16 planes
    split_bf_kernel<3><<<(M_ROWS*DIMX/4)/256, 256>>>(
        (const float4*)x, (uint2*)xs, M_ROWS*DIMX/4);

    // 4) QKV projection: all-bf16 async pipeline, split outputs
    int gsm1 = 2 * 4*128*ALDU * 4;
    cudaFuncSetAttribute(gemm_async<3,true>,
                         cudaFuncAttributeMaxDynamicSharedMemorySize, gsm1);
    gemm_async<3,true><<<dim3(QKV_N/128, M_ROWS/128), 256, gsm1>>>(
        xs, w3, qh, ql, M_ROWS, QKV_N, DIMX);

    // 5) attention (GQA-merged)
    int fsm = (256*QPAD*2 + 64*QPAD*2 + 64*VPAD) * 4;
    cudaFuncSetAttribute(flash_kernel,
                         cudaFuncAttributeMaxDynamicSharedMemorySize, fsm);
    flash_kernel<<<dim3(16, 32), 256, fsm>>>(qh, ql, ao);

    // 6) pre-split ao into 2 bf16 planes
    split_bf_kernel<2><<<(M_ROWS*DIMX/4)/256, 256>>>(
        (const float4*)ao, (uint2*)aos, M_ROWS*DIMX/4);

    // 7) output projection
    int gsm2 = 2 * 3*128*ALDU * 4;
    cudaFuncSetAttribute(gemm_async<2,false>,
                         cudaFuncAttributeMaxDynamicSharedMemorySize, gsm2);
    gemm_async<2,false><<<dim3(DIMX/128, M_ROWS/128), 256, gsm2>>>(
        aos, to, out, nullptr, M_ROWS, DIMX, DIMX);
}

// round 12
// speedup vs baseline: 1.1312x; 1.0714x over previous
#include <cuda_runtime.h>
#include <cuda_bf16.h>
#include <math.h>
#include <stdint.h>

#define DIMX 2048
#define KVDIM 512
#define QKV_N 3072
#define HD 64
#define NH 32
#define BATCH 2
#define SEQ 2048
#define M_ROWS (BATCH*SEQ)
#define QPAD 68     // float2 stride for Q/K interleaved hi/lo smem (flash)
#define VPAD 72     // float stride for V smem (flash)
#define ALDU 20     // uint32 row stride for bf16-pair smem tiles (GEMM)

// ---- scratch (module-static device memory) ----
__device__ __align__(16) __nv_bfloat16 g_w  [QKV_N*DIMX];       // ternarized [wq;wk;wv]
__device__ __align__(16) __nv_bfloat16 g_to [DIMX*DIMX];        // ternarized wo
__device__ __align__(16) __nv_bfloat16 g_xs [(size_t)3*M_ROWS*DIMX];  // x 3-split planes
__device__ __align__(16) __nv_bfloat16 g_aos[(size_t)2*M_ROWS*DIMX];  // ao 2-split planes
__device__ float g_qh [(size_t)M_ROWS*QKV_N];
__device__ float g_ql [(size_t)M_ROWS*QKV_N];
__device__ float g_ao [(size_t)M_ROWS*DIMX];
__device__ float g_partial[4][256];
__device__ float g_thresh[4];

__device__ __forceinline__ uint32_t f2tf(float f) {
    uint32_t u; asm("cvt.rna.tf32.f32 %0, %1;" : "=r"(u) : "f"(f)); return u;
}
__device__ __forceinline__ float f2tff(float f) { return __uint_as_float(f2tf(f)); }
__device__ __forceinline__ uint32_t fu(float f) { return __float_as_uint(f); }
__device__ __forceinline__ void split2(float v, float& hi, float& lo) {
    hi = f2tff(v);
    lo = f2tff(v - hi);
}
__device__ __forceinline__ float bfr(float v) {
    return __bfloat162float(__float2bfloat16(v));
}
__device__ __forceinline__ uint32_t packbf(float a, float b) {
    __nv_bfloat162 p = __floats2bfloat162_rn(a, b);
    return *reinterpret_cast<uint32_t*>(&p);
}
__device__ __forceinline__ uint32_t smem_u32(const void* p) {
    uint32_t a;
    asm("{ .reg .u64 t; cvta.to.shared.u64 t, %1; cvt.u32.u64 %0, t; }" : "=r"(a) : "l"(p));
    return a;
}
#define CP16(dst, src) \
    asm volatile("cp.async.cg.shared.global [%0], [%1], 16;" :: "r"(dst), "l"(src))
#define CP_COMMIT()  asm volatile("cp.async.commit_group;" ::: "memory")
#define CP_WAIT1()   asm volatile("cp.async.wait_group 1;" ::: "memory")

#define LDSM_X4(r0, r1, r2, r3, addr) \
    asm volatile("ldmatrix.sync.aligned.m8n8.x4.shared.b16 {%0,%1,%2,%3}, [%4];" \
        : "=r"(r0), "=r"(r1), "=r"(r2), "=r"(r3) : "r"(addr))

// ---- fused |w| mean, pass 1 (grid.y = slot) ----
__global__ void abs_all_kernel(const float4* __restrict__ wq, const float4* __restrict__ wk,
                               const float4* __restrict__ wv, const float4* __restrict__ wo) {
    __shared__ float sd[256];
    int slot = blockIdx.y;
    const float4* w = slot == 0 ? wq : slot == 1 ? wk : slot == 2 ? wv : wo;
    int n4 = (slot == 0 || slot == 3) ? DIMX*DIMX/4 : KVDIM*DIMX/4;
    float s = 0.f;
    int stride = gridDim.x * blockDim.x;
    for (int i = blockIdx.x*blockDim.x + threadIdx.x; i < n4; i += stride) {
        float4 v = w[i];
        s += fabsf(v.x) + fabsf(v.y) + fabsf(v.z) + fabsf(v.w);
    }
    sd[threadIdx.x] = s;
    __syncthreads();
    for (int st = 128; st; st >>= 1) {
        if (threadIdx.x < st) sd[threadIdx.x] += sd[threadIdx.x + st];
        __syncthreads();
    }
    if (threadIdx.x == 0) g_partial[slot][blockIdx.x] = sd[0];
}

__global__ void finalize_kernel() {
    int slot = blockIdx.x;
    __shared__ float sd[256];
    sd[threadIdx.x] = g_partial[slot][threadIdx.x];
    __syncthreads();
    for (int st = 128; st; st >>= 1) {
        if (threadIdx.x < st) sd[threadIdx.x] += sd[threadIdx.x + st];
        __syncthreads();
    }
    if (threadIdx.x == 0) {
        const int ncounts[4] = {DIMX*DIMX, KVDIM*DIMX, KVDIM*DIMX, DIMX*DIMX};
        float scale = sd[0] / (float)ncounts[slot];
        g_thresh[slot] = 0.05f * fmaxf(scale, 1e-6f);
    }
}

// ---- fused ternarize -> bf16 (grid.y = slot) ----
__global__ void tern_all_kernel(const float4* __restrict__ wq, const float4* __restrict__ wk,
                                const float4* __restrict__ wv, const float4* __restrict__ wo,
                                uint2* __restrict__ w3, uint2* __restrict__ to) {
    int slot = blockIdx.y;
    int n4 = (slot == 0 || slot == 3) ? DIMX*DIMX/4 : KVDIM*DIMX/4;
    int i = blockIdx.x*256 + threadIdx.x;
    if (i >= n4) return;
    const float4* w = slot == 0 ? wq : slot == 1 ? wk : slot == 2 ? wv : wo;
    uint2* dst = slot == 0 ? w3
               : slot == 1 ? (w3 + DIMX*DIMX/4)
               : slot == 2 ? (w3 + DIMX*DIMX/4 + KVDIM*DIMX/4)
               : to;
    float th = g_thresh[slot];
    float4 v = w[i];
    float o0 = v.x > th ? 1.f : (v.x < -th ? -1.f : 0.f);
    float o1 = v.y > th ? 1.f : (v.y < -th ? -1.f : 0.f);
    float o2 = v.z > th ? 1.f : (v.z < -th ? -1.f : 0.f);
    float o3 = v.w > th ? 1.f : (v.w < -th ? -1.f : 0.f);
    dst[i] = make_uint2(packbf(o0, o1), packbf(o2, o3));
}

// ---- split fp32 -> NS bf16 planes ----
template<int NS>
__global__ void split_bf_kernel(const float4* __restrict__ src, uint2* __restrict__ dst, int n4) {
    int i = blockIdx.x*256 + threadIdx.x;
    if (i >= n4) return;
    float4 v = src[i];
    float h0 = bfr(v.x), h1 = bfr(v.y), h2 = bfr(v.z), h3 = bfr(v.w);
    dst[i] = make_uint2(packbf(h0, h1), packbf(h2, h3));
    float r0 = v.x - h0, r1 = v.y - h1, r2 = v.z - h2, r3 = v.w - h3;
    if (NS == 2) {
        dst[i + (size_t)n4] = make_uint2(packbf(r0, r1), packbf(r2, r3));
    } else {
        float m0 = bfr(r0), m1 = bfr(r1), m2 = bfr(r2), m3 = bfr(r3);
        dst[i + (size_t)n4] = make_uint2(packbf(m0, m1), packbf(m2, m3));
        dst[i + (size_t)2*n4] =
            make_uint2(packbf(r0 - m0, r1 - m1), packbf(r2 - m2, r3 - m3));
    }
}

#define MMA_BF16(d, a, b0v, b1v)                                             \
    asm volatile("mma.sync.aligned.m16n8k16.row.col.f32.bf16.bf16.f32 "      \
        "{%0,%1,%2,%3}, {%4,%5,%6,%7}, {%8,%9}, {%0,%1,%2,%3};"              \
        : "+f"(d[0]), "+f"(d[1]), "+f"(d[2]), "+f"(d[3])                     \
        : "r"(a[0]), "r"(a[1]), "r"(a[2]), "r"(a[3]), "r"(b0v), "r"(b1v))

#define MMA_TF32(d, a, b0v, b1v)                                             \
    asm volatile("mma.sync.aligned.m16n8k8.row.col.f32.tf32.tf32.f32 "       \
        "{%0,%1,%2,%3}, {%4,%5,%6,%7}, {%8,%9}, {%0,%1,%2,%3};"              \
        : "+f"(d[0]), "+f"(d[1]), "+f"(d[2]), "+f"(d[3])                     \
        : "r"(a[0]), "r"(a[1]), "r"(a[2]), "r"(a[3]), "r"(b0v), "r"(b1v))

// ---- C[M,N] = A*B^T, all-bf16 cp.async pipeline + ldmatrix fragments ----
template<int NSPLIT, bool SPLIT_OUT>
__global__ __launch_bounds__(256) void gemm_async(
    const __nv_bfloat16* __restrict__ Abf, const __nv_bfloat16* __restrict__ B,
    float* __restrict__ C, float* __restrict__ Clo, int Mtot, int N, int K)
{
    extern __shared__ __align__(16) uint32_t smu[];
    const int STG_U32 = (NSPLIT+1)*128*ALDU;
    int tid = threadIdx.x;
    int wid = tid >> 5, lane = tid & 31;
    int g = lane >> 2, t = lane & 3;
    int wm = (wid & 1) * 64, wn = (wid >> 1) * 32;
    int lr = tid >> 1, half = tid & 1;

    // ldmatrix lane decomposition
    int lrow8 = lane & 7;
    int lsel  = lane >> 3;              // 0..3 (matrix select)
    int a_row_add = (lsel & 1) << 3;    // +8 rows for matrices 1,3
    int a_col_add = (lsel >> 1) << 2;   // +4 uint32 (k+8) for matrices 2,3
    int b_row_add = (lsel >> 1) << 3;   // +8 n-rows for matrices 2,3
    int b_col_add = (lsel & 1) << 2;    // +4 uint32 (k+8) for matrices 1,3

    uint32_t sb = smem_u32(smu);
    uint32_t stBase[2] = { sb, sb + (uint32_t)STG_U32*4 };

    int brow = blockIdx.y*128 + lr;
    const __nv_bfloat16* Brow = B + (size_t)(blockIdx.x*128 + lr)*K;

    float acc[4][4][4];
    #pragma unroll
    for (int mt = 0; mt < 4; mt++)
        #pragma unroll
        for (int nt = 0; nt < 4; nt++)
            #pragma unroll
            for (int r = 0; r < 4; r++) acc[mt][nt][r] = 0.f;

    auto issue = [&](int c, int stg) {
        int k0 = c*32;
        #pragma unroll
        for (int sp = 0; sp < NSPLIT; sp++) {
            const __nv_bfloat16* src = Abf + ((size_t)sp*Mtot + brow)*K + k0 + half*16;
            uint32_t dst = stBase[stg] + (uint32_t)((sp*128 + lr)*ALDU + half*8)*4;
            CP16(dst, src);
            CP16(dst + 16, src + 8);
        }
        const __nv_bfloat16* bs = Brow + k0 + half*16;
        uint32_t dstb = stBase[stg] + (uint32_t)((NSPLIT*128 + lr)*ALDU + half*8)*4;
        CP16(dstb, bs);
        CP16(dstb + 16, bs + 8);
        CP_COMMIT();
    };

    int nch = K/32;
    issue(0, 0);
    issue(1, 1);

    for (int c = 0; c < nch; c++) {
        CP_WAIT1();
        __syncthreads();
        int stg = c & 1;
        uint32_t stAddr = stBase[stg];
        #pragma unroll
        for (int s = 0; s < 2; s++) {
            uint32_t a[NSPLIT][4][4], b[4][2];
            #pragma unroll
            for (int mt = 0; mt < 4; mt++) {
                #pragma unroll
                for (int sp = 0; sp < NSPLIT; sp++) {
                    uint32_t addr = stAddr + 4u*(
                        (uint32_t)(sp*128 + wm + mt*16 + lrow8 + a_row_add)*ALDU
                        + s*8 + a_col_add);
                    LDSM_X4(a[sp][mt][0], a[sp][mt][1], a[sp][mt][2], a[sp][mt][3], addr);
                }
            }
            #pragma unroll
            for (int ntp = 0; ntp < 2; ntp++) {
                uint32_t addr = stAddr + 4u*(
                    (uint32_t)(NSPLIT*128 + wn + ntp*16 + b_row_add + lrow8)*ALDU
                    + s*8 + b_col_add);
                uint32_t r0, r1, r2, r3;
                LDSM_X4(r0, r1, r2, r3, addr);
                b[ntp*2][0]   = r0; b[ntp*2][1]   = r1;
                b[ntp*2+1][0] = r2; b[ntp*2+1][1] = r3;
            }
            #pragma unroll
            for (int mt = 0; mt < 4; mt++)
                #pragma unroll
                for (int nt = 0; nt < 4; nt++)
                    #pragma unroll
                    for (int sp = 0; sp < NSPLIT; sp++)
                        MMA_BF16(acc[mt][nt], a[sp][mt], b[nt][0], b[nt][1]);
        }
        __syncthreads();
        if (c + 2 < nch) issue(c + 2, stg);
        else CP_COMMIT();   // keep group count aligned for CP_WAIT1
    }

    #pragma unroll
    for (int mt = 0; mt < 4; mt++) {
        int r0 = blockIdx.y*128 + wm + mt*16 + g;
        #pragma unroll
        for (int nt = 0; nt < 4; nt++) {
            int c = blockIdx.x*128 + wn + nt*8 + t*2;
            if (SPLIT_OUT) {
                float h0,l0,h1,l1,h2,l2,h3,l3;
                split2(acc[mt][nt][0], h0, l0); split2(acc[mt][nt][1], h1, l1);
                split2(acc[mt][nt][2], h2, l2); split2(acc[mt][nt][3], h3, l3);
                *reinterpret_cast<float2*>(C   + (size_t)r0*N + c)     = make_float2(h0, h1);
                *reinterpret_cast<float2*>(Clo + (size_t)r0*N + c)     = make_float2(l0, l1);
                *reinterpret_cast<float2*>(C   + (size_t)(r0+8)*N + c) = make_float2(h2, h3);
                *reinterpret_cast<float2*>(Clo + (size_t)(r0+8)*N + c) = make_float2(l2, l3);
            } else {
                *reinterpret_cast<float2*>(C + (size_t)r0*N + c) =
                    make_float2(acc[mt][nt][0], acc[mt][nt][1]);
                *reinterpret_cast<float2*>(C + (size_t)(r0+8)*N + c) =
                    make_float2(acc[mt][nt][2], acc[mt][nt][3]);
            }
        }
    }
}

// ---- GQA-merged causal flash attention (R10 body, unchanged) ----
__global__ __launch_bounds__(256) void flash_kernel(
    const float* __restrict__ Qhi, const float* __restrict__ Qlo,
    float* __restrict__ O)
{
    extern __shared__ float smf[];
    float2* Qs = reinterpret_cast<float2*>(smf);
    float2* Ks = reinterpret_cast<float2*>(smf + 256*QPAD*2);
    float*  Vs = smf + 256*QPAD*2 + 64*QPAD*2;

    int gcomb = blockIdx.x;
    int gkv = gcomb >> 1;
    int b   = gcomb & 1;
    int qb  = 31 - blockIdx.y;

    int tid = threadIdx.x;
    int wid = tid >> 5, lane = tid & 31;
    int g = lane >> 2, t = lane & 3;
    int hh = wid >> 1;
    int h  = gkv*4 + hh;
    int wr = (wid & 1) * 32;

    {
        size_t rowbase = (size_t)(b*SEQ + qb*64);
        #pragma unroll
        for (int it = 0; it < 32; it++) {
            int pidx = tid + it*256;
            int qrow = pidx >> 5;
            int c2 = pidx & 31;
            int head = gkv*4 + (qrow >> 6);
            size_t goff = (rowbase + (qrow & 63))*QKV_N + head*HD + c2*2;
            float2 hv = *reinterpret_cast<const float2*>(Qhi + goff);
            float2 lv = *reinterpret_cast<const float2*>(Qlo + goff);
            *reinterpret_cast<float4*>(&Qs[qrow*QPAD + c2*2]) =
                make_float4(hv.x, lv.x, hv.y, lv.y);
        }
    }

    float m_i[4], l_i[4];
    float o_acc[2][8][4];
    #pragma unroll
    for (int i = 0; i < 4; i++) { m_i[i] = -INFINITY; l_i[i] = 0.f; }
    #pragma unroll
    for (int mt = 0; mt < 2; mt++)
        #pragma unroll
        for (int dt = 0; dt < 8; dt++)
            #pragma unroll
            for (int r = 0; r < 4; r++) o_acc[mt][dt][r] = 0.f;

    for (int kb = 0; kb <= qb; kb++) {
        __syncthreads();
        {
            size_t krowbase = (size_t)(b*SEQ + kb*64);
            #pragma unroll
            for (int it = 0; it < 8; it++) {
                int pidx = tid + it*256;
                int kr = pidx >> 5, c2 = pidx & 31;
                size_t goff = (krowbase + kr)*QKV_N + DIMX + gkv*HD + c2*2;
                float2 hv = *reinterpret_cast<const float2*>(Qhi + goff);
                float2 lv = *reinterpret_cast<const float2*>(Qlo + goff);
                *reinterpret_cast<float4*>(&Ks[kr*QPAD + c2*2]) =
                    make_float4(hv.x, lv.x, hv.y, lv.y);
            }
            #pragma unroll
            for (int it = 0; it < 4; it++) {
                int fidx = tid + it*256;
                int vr = fidx >> 4, d4 = fidx & 15;
                size_t goff = (krowbase + vr)*QKV_N + DIMX + KVDIM + gkv*HD + d4*4;
                *reinterpret_cast<float4*>(&Vs[vr*VPAD + d4*4]) =
                    *reinterpret_cast<const float4*>(Qhi + goff);
            }
        }
        __syncthreads();

        float s[2][8][4];
        #pragma unroll
        for (int mt = 0; mt < 2; mt++)
            #pragma unroll
            for (int nt = 0; nt < 8; nt++)
                #pragma unroll
                for (int r = 0; r < 4; r++) s[mt][nt][r] = 0.f;

        #pragma unroll
        for (int ks = 0; ks < 8; ks++) {
            int kk = ks*8;
            uint32_t ah[2][4], al[2][4];
            #pragma unroll
            for (int mt = 0; mt < 2; mt++) {
                int row = hh*64 + wr + mt*16 + g;
                float2 q00 = Qs[row*QPAD + kk + t];
                float2 q01 = Qs[row*QPAD + kk + t + 4];
                float2 q10 = Qs[(row+8)*QPAD + kk + t];
                float2 q11 = Qs[(row+8)*QPAD + kk + t + 4];
                ah[mt][0] = fu(q00.x); al[mt][0] = fu(q00.y);
                ah[mt][1] = fu(q10.x); al[mt][1] = fu(q10.y);
                ah[mt][2] = fu(q01.x); al[mt][2] = fu(q01.y);
                ah[mt][3] = fu(q11.x); al[mt][3] = fu(q11.y);
            }
            #pragma unroll
            for (int nt = 0; nt < 8; nt++) {
                float2 k0 = Ks[(nt*8+g)*QPAD + kk + t];
                float2 k1 = Ks[(nt*8+g)*QPAD + kk + t + 4];
                uint32_t bh0 = fu(k0.x), bl0 = fu(k0.y);
                uint32_t bh1 = fu(k1.x), bl1 = fu(k1.y);
                #pragma unroll
                for (int mt = 0; mt < 2; mt++) {
                    MMA_TF32(s[mt][nt], ah[mt], bh0, bh1);
                    MMA_TF32(s[mt][nt], ah[mt], bl0, bl1);
                    MMA_TF32(s[mt][nt], al[mt], bh0, bh1);
                }
            }
        }

        const float smul = 0.125f;
        if (kb == qb) {
            #pragma unroll
            for (int mt = 0; mt < 2; mt++) {
                int qr = wr + mt*16 + g;
                #pragma unroll
                for (int nt = 0; nt < 8; nt++) {
                    int c0 = nt*8 + t*2;
                    s[mt][nt][0] = (c0     <= qr)     ? s[mt][nt][0]*smul : -INFINITY;
                    s[mt][nt][1] = (c0 + 1 <= qr)     ? s[mt][nt][1]*smul : -INFINITY;
                    s[mt][nt][2] = (c0     <= qr + 8) ? s[mt][nt][2]*smul : -INFINITY;
                    s[mt][nt][3] = (c0 + 1 <= qr + 8) ? s[mt][nt][3]*smul : -INFINITY;
                }
            }
        } else {
            #pragma unroll
            for (int mt = 0; mt < 2; mt++)
                #pragma unroll
                for (int nt = 0; nt < 8; nt++)
                    #pragma unroll
                    for (int r = 0; r < 4; r++) s[mt][nt][r] *= smul;
        }

        #pragma unroll
        for (int mt = 0; mt < 2; mt++)
            #pragma unroll
            for (int rr = 0; rr < 2; rr++) {
                int si = mt*2 + rr;
                float mx = -INFINITY;
                #pragma unroll
                for (int nt = 0; nt < 8; nt++)
                    mx = fmaxf(mx, fmaxf(s[mt][nt][2*rr], s[mt][nt][2*rr+1]));
                mx = fmaxf(mx, __shfl_xor_sync(0xffffffffu, mx, 1));
                mx = fmaxf(mx, __shfl_xor_sync(0xffffffffu, mx, 2));
                float m_new = fmaxf(m_i[si], mx);
                float alpha = __expf(m_i[si] - m_new);
                float rs = 0.f;
                #pragma unroll
                for (int nt = 0; nt < 8; nt++) {
                    float p0 = __expf(s[mt][nt][2*rr]   - m_new);
                    float p1 = __expf(s[mt][nt][2*rr+1] - m_new);
                    s[mt][nt][2*rr] = p0; s[mt][nt][2*rr+1] = p1;
                    rs += p0 + p1;
                }
                rs += __shfl_xor_sync(0xffffffffu, rs, 1);
                rs += __shfl_xor_sync(0xffffffffu, rs, 2);
                l_i[si] = l_i[si]*alpha + rs;
                m_i[si] = m_new;
                #pragma unroll
                for (int dt = 0; dt < 8; dt++) {
                    o_acc[mt][dt][2*rr]   *= alpha;
                    o_acc[mt][dt][2*rr+1] *= alpha;
                }
            }

        #pragma unroll
        for (int ks = 0; ks < 8; ks++) {
            int kk = ks*8;
            uint32_t pa[2][4];
            int srcA = (lane & 28) | (t >> 1);
            int srcB = srcA + 2;
            #pragma unroll
            for (int mt = 0; mt < 2; mt++) {
                float x0 = __shfl_sync(0xffffffffu, s[mt][ks][0], srcA);
                float x1 = __shfl_sync(0xffffffffu, s[mt][ks][1], srcA);
                float y0 = __shfl_sync(0xffffffffu, s[mt][ks][0], srcB);
                float y1 = __shfl_sync(0xffffffffu, s[mt][ks][1], srcB);
                float x2 = __shfl_sync(0xffffffffu, s[mt][ks][2], srcA);
                float x3 = __shfl_sync(0xffffffffu, s[mt][ks][3], srcA);
                float y2 = __shfl_sync(0xffffffffu, s[mt][ks][2], srcB);
                float y3 = __shfl_sync(0xffffffffu, s[mt][ks][3], srcB);
                float a0 = (t & 1) ? x1 : x0;
                float a1 = (t & 1) ? x3 : x2;
                float a2 = (t & 1) ? y1 : y0;
                float a3 = (t & 1) ? y3 : y2;
                pa[mt][0] = f2tf(a0); pa[mt][1] = f2tf(a1);
                pa[mt][2] = f2tf(a2); pa[mt][3] = f2tf(a3);
            }
            #pragma unroll
            for (int dt = 0; dt < 8; dt++) {
                uint32_t v0 = fu(Vs[(kk+t)*VPAD + dt*8 + g]);
                uint32_t v1 = fu(Vs[(kk+t+4)*VPAD + dt*8 + g]);
                MMA_TF32(o_acc[0][dt], pa[0], v0, v1);
                MMA_TF32(o_acc[1][dt], pa[1], v0, v1);
            }
        }
    }

    #pragma unroll
    for (int mt = 0; mt < 2; mt++) {
        float inv0 = 1.f / l_i[mt*2];
        float inv1 = 1.f / l_i[mt*2+1];
        float* Og = O + (size_t)(b*SEQ + qb*64 + wr + mt*16 + g)*DIMX + h*HD;
        #pragma unroll
        for (int dt = 0; dt < 8; dt++) {
            *reinterpret_cast<float2*>(Og + dt*8 + t*2) =
                make_float2(o_acc[mt][dt][0]*inv0, o_acc[mt][dt][1]*inv0);
            *reinterpret_cast<float2*>(Og + (size_t)8*DIMX + dt*8 + t*2) =
                make_float2(o_acc[mt][dt][2]*inv1, o_acc[mt][dt][3]*inv1);
        }
    }
}

extern "C" void kernel_launch(void* const* d_in, const int* in_sizes, int n_in,
                              void* d_out, int out_size)
{
    const float* x  = (const float*)d_in[0];
    const float* wq = (const float*)d_in[1];
    const float* wk = (const float*)d_in[2];
    const float* wv = (const float*)d_in[3];
    const float* wo = (const float*)d_in[4];
    float* out = (float*)d_out;

    __nv_bfloat16 *w3, *to, *xs, *aos;
    float *qh, *ql, *ao;
    cudaGetSymbolAddress((void**)&w3,  g_w);
    cudaGetSymbolAddress((void**)&to,  g_to);
    cudaGetSymbolAddress((void**)&xs,  g_xs);
    cudaGetSymbolAddress((void**)&aos, g_aos);
    cudaGetSymbolAddress((void**)&qh,  g_qh);
    cudaGetSymbolAddress((void**)&ql,  g_ql);
    cudaGetSymbolAddress((void**)&ao,  g_ao);

    // 1) fused |w| mean + thresholds
    abs_all_kernel<<<dim3(256, 4), 256>>>((const float4*)wq, (const float4*)wk,
                                          (const float4*)wv, (const float4*)wo);
    finalize_kernel<<<4, 256>>>();

    // 2) fused ternarize -> bf16
    tern_all_kernel<<<dim3(DIMX*DIMX/4/256, 4), 256>>>(
        (const float4*)wq, (const float4*)wk, (const float4*)wv, (const float4*)wo,
        (uint2*)w3, (uint2*)to);

    // 3) pre-split x into 3 bf16 planes
    split_bf_kernel<3><<<(M_ROWS*DIMX/4)/256, 256>>>(
        (const float4*)x, (uint2*)xs, M_ROWS*DIMX/4);

    // 4) QKV projection
    int gsm1 = 2 * 4*128*ALDU * 4;
    cudaFuncSetAttribute(gemm_async<3,true>,
                         cudaFuncAttributeMaxDynamicSharedMemorySize, gsm1);
    gemm_async<3,true><<<dim3(QKV_N/128, M_ROWS/128), 256, gsm1>>>(
        xs, w3, qh, ql, M_ROWS, QKV_N, DIMX);

    // 5) attention (GQA-merged)
    int fsm = (256*QPAD*2 + 64*QPAD*2 + 64*VPAD) * 4;
    cudaFuncSetAttribute(flash_kernel,
                         cudaFuncAttributeMaxDynamicSharedMemorySize, fsm);
    flash_kernel<<<dim3(16, 32), 256, fsm>>>(qh, ql, ao);

    // 6) pre-split ao into 2 bf16 planes
    split_bf_kernel<2><<<(M_ROWS*DIMX/4)/256, 256>>>(
        (const float4*)ao, (uint2*)aos, M_ROWS*DIMX/4);

    // 7) output projection
    int gsm2 = 2 * 3*128*ALDU * 4;
    cudaFuncSetAttribute(gemm_async<2,false>,
                         cudaFuncAttributeMaxDynamicSharedMemorySize, gsm2);
    gemm_async<2,false><<<dim3(DIMX/128, M_ROWS/128), 256, gsm2>>>(
        aos, to, out, nullptr, M_ROWS, DIMX, DIMX);
}